// round 2
// baseline (speedup 1.0000x reference)
#include <cuda_runtime.h>
#include <math.h>

// Problem constants
#define T_SEQ 4096
#define D_MODEL 2048
#define N_HEADS 16
#define N_KV 4
#define DH 128
#define HALF 64
#define KV_DIM 512   // N_KV * DH

// Scratch (device globals; no allocation allowed)
__device__ float g_q[T_SEQ * D_MODEL];
__device__ float g_k[T_SEQ * KV_DIM];
__device__ float g_v[T_SEQ * KV_DIM];
__device__ float g_y[T_SEQ * D_MODEL];

// ---------------------------------------------------------------------------
// SGEMM: C[M,N] = A[M,K] @ B[K,N], all row-major fp32.
// 128x128 tile, BK=16, 256 threads, 8x8 micro-tile per thread.
// ---------------------------------------------------------------------------
__global__ __launch_bounds__(256)
void sgemm128(const float* __restrict__ A, const float* __restrict__ B,
              float* __restrict__ C, int M, int N, int K) {
    __shared__ float As[16][132];   // [k][m], padded (2-way max on store)
    __shared__ float Bs[16][128];   // [k][n]

    const int tid = threadIdx.x;
    const int tx = tid & 15;        // n-group
    const int ty = tid >> 4;        // m-group
    const int m0 = blockIdx.y * 128;
    const int n0 = blockIdx.x * 128;

    float acc[8][8];
#pragma unroll
    for (int i = 0; i < 8; ++i)
#pragma unroll
        for (int j = 0; j < 8; ++j) acc[i][j] = 0.f;

    for (int k0 = 0; k0 < K; k0 += 16) {
        // Load A tile 128x16 (float4 along K, transposed store)
#pragma unroll
        for (int l = 0; l < 2; ++l) {
            int lin = tid + l * 256;        // float4 index, 512 total
            int r = lin >> 2;               // 0..127
            int kq = (lin & 3) << 2;        // 0,4,8,12
            float4 av = *(const float4*)(A + (size_t)(m0 + r) * K + k0 + kq);
            As[kq + 0][r] = av.x;
            As[kq + 1][r] = av.y;
            As[kq + 2][r] = av.z;
            As[kq + 3][r] = av.w;
        }
        // Load B tile 16x128 (float4 along N, direct)
#pragma unroll
        for (int l = 0; l < 2; ++l) {
            int lin = tid + l * 256;
            int r = lin >> 5;               // 0..15
            int c4 = (lin & 31) << 2;       // 0..124
            *(float4*)(&Bs[r][c4]) =
                *(const float4*)(B + (size_t)(k0 + r) * N + n0 + c4);
        }
        __syncthreads();

#pragma unroll
        for (int kk = 0; kk < 16; ++kk) {
            float4 a0 = *(float4*)(&As[kk][ty * 8]);
            float4 a1 = *(float4*)(&As[kk][ty * 8 + 4]);
            float4 b0 = *(float4*)(&Bs[kk][tx * 4]);
            float4 b1 = *(float4*)(&Bs[kk][64 + tx * 4]);
            float a[8] = {a0.x, a0.y, a0.z, a0.w, a1.x, a1.y, a1.z, a1.w};
            float b[8] = {b0.x, b0.y, b0.z, b0.w, b1.x, b1.y, b1.z, b1.w};
#pragma unroll
            for (int i = 0; i < 8; ++i)
#pragma unroll
                for (int j = 0; j < 8; ++j) acc[i][j] += a[i] * b[j];
        }
        __syncthreads();
    }

    // Write C: rows m0+ty*8+i, cols n0+tx*4+j (j<4) and n0+64+tx*4+(j-4)
#pragma unroll
    for (int i = 0; i < 8; ++i) {
        float* cp = C + (size_t)(m0 + ty * 8 + i) * N + n0;
        *(float4*)(cp + tx * 4)      = make_float4(acc[i][0], acc[i][1], acc[i][2], acc[i][3]);
        *(float4*)(cp + 64 + tx * 4) = make_float4(acc[i][4], acc[i][5], acc[i][6], acc[i][7]);
    }
}

// ---------------------------------------------------------------------------
// RoPE in-place on [T, nheads, 128] buffers (rowstride = nheads*128)
// ---------------------------------------------------------------------------
__global__ void rope_kernel(float* __restrict__ buf, int nheads, int rowstride) {
    int idx = blockIdx.x * blockDim.x + threadIdx.x;
    int total = T_SEQ * nheads * HALF;
    if (idx >= total) return;
    int i = idx & (HALF - 1);
    int h = (idx >> 6) % nheads;
    int t = idx / (HALF * nheads);

    float inv = powf(10000.f, -(float)i / (float)HALF);
    float ang = (float)t * inv;
    float s, c;
    sincosf(ang, &s, &c);

    float* base = buf + (size_t)t * rowstride + h * DH;
    float x1 = base[i];
    float x2 = base[i + HALF];
    base[i]        = x1 * c - x2 * s;
    base[i + HALF] = x1 * s + x2 * c;
}

// ---------------------------------------------------------------------------
// Flash attention (causal, GQA): per CTA one (query-block of 64, head).
// Qt/Kt stored d-major [128][64] with XOR swizzle for conflict-free LDS.128.
// Vs [64][128] natural, Pt [64][68] padded.
// 256 threads: tx=tid&15 (S cols / O cols), ty=tid>>4 (rows: ty*4..ty*4+3)
// ---------------------------------------------------------------------------
#define QT_OFF 0
#define KT_OFF 8192
#define VS_OFF 16384
#define PT_OFF 24576
#define SMEM_FLOATS (24576 + 64 * 68)
#define SMEM_BYTES (SMEM_FLOATS * 4)

__global__ __launch_bounds__(256)
void attn_kernel(const float* __restrict__ q, const float* __restrict__ k,
                 const float* __restrict__ v, float* __restrict__ y) {
    extern __shared__ float sm[];
    float* Qt = sm + QT_OFF;
    float* Kt = sm + KT_OFF;
    float* Vs = sm + VS_OFF;
    float* Pt = sm + PT_OFF;

    const int qb = blockIdx.x;          // query block (64 rows)
    const int hq = blockIdx.y;          // query head 0..15
    const int hkv = hq >> 2;            // kv head (GROUP = 4)
    const int tid = threadIdx.x;
    const int tx = tid & 15;
    const int ty = tid >> 4;
    const int q0 = qb * 64;

    // ---- Load Q tile transposed+swizzled: element (r,d) -> Qt[d][swz(r,d)]
#pragma unroll
    for (int l = 0; l < 8; ++l) {
        int lin = tid + l * 256;        // float4 index over 64x32
        int r = lin >> 5;               // query row in tile
        int d4 = lin & 31;
        int d = d4 << 2;
        float4 val = *(const float4*)(q + (size_t)(q0 + r) * D_MODEL + hq * DH + d);
        int g = r >> 2, ci = r & 3;
        int gs = (g ^ (d4 & 15)) << 2;
        Qt[(d + 0) * 64 + gs + ci] = val.x;
        Qt[(d + 1) * 64 + gs + ci] = val.y;
        Qt[(d + 2) * 64 + gs + ci] = val.z;
        Qt[(d + 3) * 64 + gs + ci] = val.w;
    }

    float m_i[4], l_i[4], acc[4][8];
#pragma unroll
    for (int i = 0; i < 4; ++i) {
        m_i[i] = -1e30f;
        l_i[i] = 0.f;
#pragma unroll
        for (int j = 0; j < 8; ++j) acc[i][j] = 0.f;
    }

    const float scale = 0.08838834764831845f;   // 1/sqrt(128)

    for (int jb = 0; jb <= qb; ++jb) {
        const int j0 = jb * 64;
        __syncthreads();   // protect Kt/Vs/Pt from previous iteration readers

        // Load K tile transposed+swizzled, V tile natural
#pragma unroll
        for (int l = 0; l < 8; ++l) {
            int lin = tid + l * 256;
            int r = lin >> 5;
            int d4 = lin & 31;
            int d = d4 << 2;
            float4 kv4 = *(const float4*)(k + (size_t)(j0 + r) * KV_DIM + hkv * DH + d);
            int g = r >> 2, ci = r & 3;
            int gs = (g ^ (d4 & 15)) << 2;
            Kt[(d + 0) * 64 + gs + ci] = kv4.x;
            Kt[(d + 1) * 64 + gs + ci] = kv4.y;
            Kt[(d + 2) * 64 + gs + ci] = kv4.z;
            Kt[(d + 3) * 64 + gs + ci] = kv4.w;
            float4 vv4 = *(const float4*)(v + (size_t)(j0 + r) * KV_DIM + hkv * DH + d);
            *(float4*)(Vs + r * 128 + d) = vv4;
        }
        __syncthreads();

        // ---- S = Q K^T fragment (4x4 per thread)
        float s[4][4];
#pragma unroll
        for (int i = 0; i < 4; ++i)
#pragma unroll
            for (int j = 0; j < 4; ++j) s[i][j] = 0.f;

#pragma unroll 4
        for (int d = 0; d < 128; ++d) {
            int d4 = d >> 2;
            float4 a = *(float4*)(Qt + d * 64 + ((ty ^ (d4 & 15)) << 2));
            float4 b = *(float4*)(Kt + d * 64 + ((tx ^ (d4 & 15)) << 2));
            float av[4] = {a.x, a.y, a.z, a.w};
            float bv[4] = {b.x, b.y, b.z, b.w};
#pragma unroll
            for (int i = 0; i < 4; ++i)
#pragma unroll
                for (int j = 0; j < 4; ++j) s[i][j] += av[i] * bv[j];
        }

        // scale + causal mask (diagonal block only)
        const bool diag = (jb == qb);
#pragma unroll
        for (int i = 0; i < 4; ++i) {
            int rl = ty * 4 + i;
#pragma unroll
            for (int j = 0; j < 4; ++j) {
                int cl = tx * 4 + j;
                float sv = s[i][j] * scale;
                if (diag && cl > rl) sv = -1e30f;
                s[i][j] = sv;
            }
        }

        // ---- online softmax per row (rows shared across the 16 tx lanes)
#pragma unroll
        for (int i = 0; i < 4; ++i) {
            float mx = fmaxf(fmaxf(s[i][0], s[i][1]), fmaxf(s[i][2], s[i][3]));
#pragma unroll
            for (int off = 1; off < 16; off <<= 1)
                mx = fmaxf(mx, __shfl_xor_sync(0xffffffffu, mx, off));
            float mnew = fmaxf(m_i[i], mx);
            float alpha = __expf(m_i[i] - mnew);
            float rs = 0.f;
#pragma unroll
            for (int j = 0; j < 4; ++j) {
                float p = __expf(s[i][j] - mnew);
                s[i][j] = p;
                rs += p;
            }
#pragma unroll
            for (int off = 1; off < 16; off <<= 1)
                rs += __shfl_xor_sync(0xffffffffu, rs, off);
            l_i[i] = l_i[i] * alpha + rs;
            m_i[i] = mnew;
#pragma unroll
            for (int j = 0; j < 8; ++j) acc[i][j] *= alpha;
        }

        // ---- write P transposed: Pt[c][r]
#pragma unroll
        for (int j = 0; j < 4; ++j) {
            *(float4*)(Pt + (tx * 4 + j) * 68 + ty * 4) =
                make_float4(s[0][j], s[1][j], s[2][j], s[3][j]);
        }
        __syncthreads();

        // ---- O += P V  (contraction over 64 keys)
#pragma unroll 4
        for (int c = 0; c < 64; ++c) {
            float4 a = *(float4*)(Pt + c * 68 + ty * 4);
            float4 b0 = *(float4*)(Vs + c * 128 + tx * 4);
            float4 b1 = *(float4*)(Vs + c * 128 + 64 + tx * 4);
            float av[4] = {a.x, a.y, a.z, a.w};
#pragma unroll
            for (int i = 0; i < 4; ++i) {
                acc[i][0] += av[i] * b0.x;
                acc[i][1] += av[i] * b0.y;
                acc[i][2] += av[i] * b0.z;
                acc[i][3] += av[i] * b0.w;
                acc[i][4] += av[i] * b1.x;
                acc[i][5] += av[i] * b1.y;
                acc[i][6] += av[i] * b1.z;
                acc[i][7] += av[i] * b1.w;
            }
        }
    }

    // ---- normalize & write y[t, hq*128 + dd]
#pragma unroll
    for (int i = 0; i < 4; ++i) {
        float inv = 1.f / l_i[i];
        int t = q0 + ty * 4 + i;
        float* yp = y + (size_t)t * D_MODEL + hq * DH;
        *(float4*)(yp + tx * 4) =
            make_float4(acc[i][0] * inv, acc[i][1] * inv, acc[i][2] * inv, acc[i][3] * inv);
        *(float4*)(yp + 64 + tx * 4) =
            make_float4(acc[i][4] * inv, acc[i][5] * inv, acc[i][6] * inv, acc[i][7] * inv);
    }
}

// ---------------------------------------------------------------------------
extern "C" void kernel_launch(void* const* d_in, const int* in_sizes, int n_in,
                              void* d_out, int out_size) {
    const float* x  = (const float*)d_in[0];
    const float* Wq = (const float*)d_in[1];
    const float* Wk = (const float*)d_in[2];
    const float* Wv = (const float*)d_in[3];
    const float* Wo = (const float*)d_in[4];
    float* out = (float*)d_out;

    void *pq, *pk, *pv, *py;
    cudaGetSymbolAddress(&pq, g_q);
    cudaGetSymbolAddress(&pk, g_k);
    cudaGetSymbolAddress(&pv, g_v);
    cudaGetSymbolAddress(&py, g_y);
    float* q = (float*)pq;
    float* kf = (float*)pk;
    float* vf = (float*)pv;
    float* y = (float*)py;

    // Projections
    sgemm128<<<dim3(D_MODEL / 128, T_SEQ / 128), 256>>>(x, Wq, q, T_SEQ, D_MODEL, D_MODEL);
    sgemm128<<<dim3(KV_DIM / 128, T_SEQ / 128), 256>>>(x, Wk, kf, T_SEQ, KV_DIM, D_MODEL);
    sgemm128<<<dim3(KV_DIM / 128, T_SEQ / 128), 256>>>(x, Wv, vf, T_SEQ, KV_DIM, D_MODEL);

    // RoPE
    {
        int nq = T_SEQ * N_HEADS * HALF;
        rope_kernel<<<(nq + 255) / 256, 256>>>(q, N_HEADS, D_MODEL);
        int nk = T_SEQ * N_KV * HALF;
        rope_kernel<<<(nk + 255) / 256, 256>>>(kf, N_KV, KV_DIM);
    }

    // Attention
    cudaFuncSetAttribute(attn_kernel, cudaFuncAttributeMaxDynamicSharedMemorySize, SMEM_BYTES);
    attn_kernel<<<dim3(T_SEQ / 64, N_HEADS), 256, SMEM_BYTES>>>(q, kf, vf, y);

    // Output projection
    sgemm128<<<dim3(D_MODEL / 128, T_SEQ / 128), 256>>>(y, Wo, out, T_SEQ, D_MODEL, D_MODEL);
}